// round 17
// baseline (speedup 1.0000x reference)
#include <cuda_runtime.h>
#include <cstdint>

// sampling_map: [B=64, C=3, H=512, W=512] fp32 row-major.
// GRID=4 -> 128x128 cells; channel-sum; valid 3x3 window over 4x4 grid -> 2x2;
// argmax (TOP_K=1) -> coords (idx//2, idx%2), output [B,1,2] as FLOAT32.
// Mean factor is uniform -> argmax-invariant -> dropped.
static constexpr int B = 64;
static constexpr int C = 3;
static constexpr int H = 512;
static constexpr int W = 512;
static constexpr int W4 = W / 4;              // 128 float4 per row
static constexpr int UNITS_PER_IMG = 16;      // 32-row bands per (b,c) image
static constexpr int UNITS_PER_BATCH = C * UNITS_PER_IMG;   // 48
static constexpr int TOTAL_UNITS = B * UNITS_PER_BATCH;     // 3072
static constexpr int GRID = 592;              // 4 CTAs/SM x 148 SMs (persistent)
static constexpr int SLOTS = C * 4;           // 12 partials per cell

// Scratch (zero-init device globals).
__device__ float        g_part[B * 16 * SLOTS];  // [b][cell16][c*4+sub]
__device__ unsigned int g_ticket[B];             // per-batch completion count
__device__ unsigned int g_work;                  // dynamic work counter

__global__ __launch_bounds__(256, 4) void region_selector_kernel(
    const float* __restrict__ in, float* __restrict__ out) {
    const int t     = threadIdx.x;
    const int w     = t >> 5;
    const int lane  = t & 31;
    const int r0    = t >> 3;     // row within 32-row band
    const int lane8 = t & 7;      // 8 threads per row

    __shared__ float s_part[8][4];
    __shared__ unsigned int s_idx;

    for (;;) {
        if (t == 0) s_idx = atomicAdd(&g_work, 1u);
        __syncthreads();
        const unsigned int idx = s_idx;
        __syncthreads();   // protect s_idx before next iteration's overwrite

        if (idx >= TOTAL_UNITS) {
            // Last CTA to exit (sees the final counter value) resets for replay.
            if (t == 0 && idx == TOTAL_UNITS + GRID - 1u) g_work = 0u;
            return;
        }

        // Unit -> (b, c, band): fully contiguous 64KB span in memory order.
        const int b    = idx / UNITS_PER_BATCH;
        const int rem  = idx % UNITS_PER_BATCH;
        const int c    = rem / UNITS_PER_IMG;
        const int s16  = rem % UNITS_PER_IMG;   // 0..15: 32-row band in image
        const int gy   = s16 >> 2;              // grid row of this band
        const int sub  = s16 & 3;               // band within the 128-row cell

        const float4* __restrict__ rowp = reinterpret_cast<const float4*>(in) +
            ((size_t)(b * C + c) * H + (size_t)(s16 * 32 + r0)) * W4;

        // Full 512-col row split into 4 gx accumulators (32 float4 each).
        float acc[4];
#pragma unroll
        for (int g = 0; g < 4; g++) acc[g] = 0.0f;
#pragma unroll
        for (int g = 0; g < 4; g++) {
#pragma unroll
            for (int j = 0; j < 4; j++) {
                float4 v = __ldg(&rowp[g * 32 + lane8 + j * 8]);
                acc[g] += (v.x + v.y) + (v.z + v.w);
            }
        }

#pragma unroll
        for (int g = 0; g < 4; g++)
#pragma unroll
            for (int off = 16; off > 0; off >>= 1)
                acc[g] += __shfl_down_sync(0xFFFFFFFFu, acc[g], off);
        if (lane == 0) {
#pragma unroll
            for (int g = 0; g < 4; g++) s_part[w][g] = acc[g];
        }
        __syncthreads();

        if (t < 4) {   // t = gx
            float s = 0.0f;
#pragma unroll
            for (int ww = 0; ww < 8; ww++) s += s_part[ww][t];
            g_part[((b * 16) + (gy * 4 + t)) * SLOTS + c * 4 + sub] = s;
        }
        __threadfence();
        __syncthreads();

        if (t == 0) {
            const unsigned int done = atomicAdd(&g_ticket[b], 1u);
            if (done == UNITS_PER_BATCH - 1u) {
                // Finalize this batch (fixed-order sums -> deterministic).
                float cs[16];
#pragma unroll
                for (int k = 0; k < 16; k++) {
                    float s = 0.0f;
                    const float* p = &g_part[((b * 16) + k) * SLOTS];
#pragma unroll
                    for (int m = 0; m < SLOTS; m++) s += __ldcg(&p[m]);
                    cs[k] = s;
                }
                float ws[4];
#pragma unroll
                for (int i = 0; i < 2; i++)
#pragma unroll
                    for (int j = 0; j < 2; j++) {
                        float s2 = 0.0f;
#pragma unroll
                        for (int di = 0; di < 3; di++)
#pragma unroll
                            for (int dj = 0; dj < 3; dj++)
                                s2 += cs[(i + di) * 4 + (j + dj)];
                        ws[i * 2 + j] = s2;
                    }
                int best_idx = 0;
                float best = ws[0];
#pragma unroll
                for (int k = 1; k < 4; k++)
                    if (ws[k] > best) { best = ws[k]; best_idx = k; }
                out[b * 2 + 0] = (float)(best_idx >> 1);
                out[b * 2 + 1] = (float)(best_idx & 1);
                g_ticket[b] = 0;   // reset for graph replay
            }
        }
        __syncthreads();
    }
}

extern "C" void kernel_launch(void* const* d_in, const int* in_sizes, int n_in,
                              void* d_out, int out_size) {
    (void)in_sizes; (void)n_in; (void)out_size;
    const float* in = (const float*)d_in[0];
    float* out = (float*)d_out;
    region_selector_kernel<<<GRID, 256>>>(in, out);
}